// round 7
// baseline (speedup 1.0000x reference)
#include <cuda_runtime.h>
#include <math.h>

#define BB 2
#define LL 225
#define DD 256
#define HH 4
#define HD 64
#define BH 8
#define NROW 450
#define LP 240

// ---------------- scratch ----------------------------------------------------
__device__ __align__(16) float g_q[BH*LL*HD];
__device__ __align__(16) float g_k[BH*LL*HD];
__device__ __align__(16) float g_v[BH*LL*HD];
__device__ __align__(16) float g_S[BH*LL*LP + 16];
__device__ __align__(16) float g_A0[BH*LL*LP + 16];
__device__ __align__(16) float g_A1[BH*LL*LP + 16];
__device__ __align__(16) float g_T0[BH*LL*LP + 16];
__device__ __align__(16) float g_T1[BH*LL*LP + 16];
__device__ __align__(16) float g_P0[BH*LL*LP + 16];
__device__ __align__(16) float g_P1[BH*LL*LP + 16];
__device__ __align__(16) float g_O[NROW*DD];
__device__ float g_deg[BH*LP];

// ---------------- helpers -----------------------------------------------------
__device__ __forceinline__ float4 ld4(const float* p) { return *(const float4*)p; }
__device__ __forceinline__ float4 f4z() { return make_float4(0.f, 0.f, 0.f, 0.f); }

__device__ __forceinline__ unsigned long long pk2(float lo, float hi) {
    unsigned long long r;
    asm("mov.b64 %0,{%1,%2};" : "=l"(r) : "f"(lo), "f"(hi));
    return r;
}
__device__ __forceinline__ void fma2(unsigned long long& d,
                                     unsigned long long a, unsigned long long b) {
    asm("fma.rn.f32x2 %0,%1,%2,%0;" : "+l"(d) : "l"(a), "l"(b));
}
__device__ __forceinline__ unsigned long long mul2(unsigned long long a,
                                                   unsigned long long b) {
    unsigned long long r;
    asm("mul.rn.f32x2 %0,%1,%2;" : "=l"(r) : "l"(a), "l"(b));
    return r;
}
__device__ __forceinline__ float2 up2(unsigned long long v) {
    float2 f;
    asm("mov.b64 {%0,%1},%2;" : "=f"(f.x), "=f"(f.y) : "l"(v));
    return f;
}

// C[4][4] += A(.. x16, stride AST) * B(16 x .., stride BST), packed f32x2
template<int AST, int BST>
__device__ __forceinline__ void inner16(const float* As, const float* Bs,
                                        int ty4, int tx4, unsigned long long acc[4][2]) {
#pragma unroll
    for (int kk = 0; kk < 16; kk++) {
        float4 bv = *(const float4*)(Bs + kk*BST + tx4);
        unsigned long long b01 = pk2(bv.x, bv.y);
        unsigned long long b23 = pk2(bv.z, bv.w);
#pragma unroll
        for (int r = 0; r < 4; r++) {
            float ar = As[(ty4 + r)*AST + kk];
            unsigned long long aa = pk2(ar, ar);
            fma2(acc[r][0], aa, b01);
            fma2(acc[r][1], aa, b23);
        }
    }
}

// C[2][4] variant for 32-row tiles
template<int AST, int BST>
__device__ __forceinline__ void inner16_2(const float* As, const float* Bs,
                                          int ty2, int tx4, unsigned long long acc[2][2]) {
#pragma unroll
    for (int kk = 0; kk < 16; kk++) {
        float4 bv = *(const float4*)(Bs + kk*BST + tx4);
        unsigned long long b01 = pk2(bv.x, bv.y);
        unsigned long long b23 = pk2(bv.z, bv.w);
#pragma unroll
        for (int r = 0; r < 2; r++) {
            float ar = As[(ty2 + r)*AST + kk];
            unsigned long long aa = pk2(ar, ar);
            fma2(acc[r][0], aa, b01);
            fma2(acc[r][1], aa, b23);
        }
    }
}

// ---------------- K1: qkv projections (y = x @ W^T) ---------------------------
__global__ void qkv_kernel(const float* __restrict__ x,
                           const float* __restrict__ Wq,
                           const float* __restrict__ Wk,
                           const float* __restrict__ Wv) {
    __shared__ __align__(16) float Xs[32][20];
    __shared__ __align__(16) float Ws[16][68];
    int tx = threadIdx.x, ty = threadIdx.y;
    int tid = ty*16 + tx;                 // 0..127
    int m0 = blockIdx.y * 32;
    int c0 = blockIdx.x * 64;
    const float* W = (c0 < 256) ? Wq : (c0 < 512) ? Wk : Wv;
    int cw0 = c0 & 255;
    unsigned long long acc[4][2] = {};
    for (int k0 = 0; k0 < 256; k0 += 16) {
        { int ii = tid >> 2, f = tid & 3;
          int m = m0 + ii;
          float4 v = (m < NROW) ? ld4(x + m*256 + k0 + 4*f) : f4z();
          *(float4*)&Xs[ii][4*f] = v; }
#pragma unroll
        for (int s = 0; s < 2; s++) {
            int idx = tid + 128*s;
            int ll = idx >> 2, g = idx & 3;
            float4 w = ld4(W + (cw0 + ll)*256 + k0 + 4*g);
            Ws[4*g+0][ll] = w.x; Ws[4*g+1][ll] = w.y;
            Ws[4*g+2][ll] = w.z; Ws[4*g+3][ll] = w.w;
        }
        __syncthreads();
        inner16<20, 68>(&Xs[0][0], &Ws[0][0], ty*4, tx*4, acc);
        __syncthreads();
    }
    int which = c0 >> 8, hb = (c0 & 255) >> 6;
    float* dst = (which == 0) ? g_q : (which == 1) ? g_k : g_v;
#pragma unroll
    for (int r = 0; r < 4; r++) {
        int m = m0 + ty*4 + r;
        if (m < NROW) {
            int b = (m >= LL) ? 1 : 0;
            int l = m - b*LL;
            float2 lo = up2(acc[r][0]), hi = up2(acc[r][1]);
            *(float4*)(dst + ((b*HH + hb)*LL + l)*HD + tx*4) =
                make_float4(lo.x, lo.y, hi.x, hi.y);
        }
    }
}

// ---------------- K2: S = q @ k^T per (b,h), also zero g_deg -------------------
__global__ void s_kernel() {
    __shared__ __align__(16) float Qs[64][20];
    __shared__ __align__(16) float Ks[16][68];
    int tx = threadIdx.x, ty = threadIdx.y;
    int tid = ty*16 + tx;
    int bh = blockIdx.z;
    if (blockIdx.x == 0 && blockIdx.y == 0 && tid < LP) g_deg[bh*LP + tid] = 0.f;
    int i0 = blockIdx.y*64, j0 = blockIdx.x*64;
    const float* qb = g_q + bh*LL*HD;
    const float* kb = g_k + bh*LL*HD;
    unsigned long long acc[4][2] = {};
#pragma unroll
    for (int d0 = 0; d0 < 64; d0 += 16) {
        { int ii = tid >> 2, f = tid & 3;
          int i = i0 + ii;
          float4 v = (i < LL) ? ld4(qb + i*HD + d0 + 4*f) : f4z();
          *(float4*)&Qs[ii][4*f] = v; }
        { int ll = tid >> 2, f = tid & 3;
          int j = j0 + ll;
          float4 v = (j < LL) ? ld4(kb + j*HD + d0 + 4*f) : f4z();
          Ks[4*f+0][ll] = v.x; Ks[4*f+1][ll] = v.y;
          Ks[4*f+2][ll] = v.z; Ks[4*f+3][ll] = v.w; }
        __syncthreads();
        inner16<20, 68>(&Qs[0][0], &Ks[0][0], ty*4, tx*4, acc);
        __syncthreads();
    }
    float* Sb = g_S + bh*LL*LP;
    int jc = j0 + tx*4;
    if (jc < LP) {
#pragma unroll
        for (int r = 0; r < 4; r++) {
            int i = i0 + ty*4 + r;
            if (i < LL) {
                float2 lo = up2(acc[r][0]), hi = up2(acc[r][1]);
                *(float4*)(Sb + i*LP + jc) = make_float4(lo.x, lo.y, hi.x, hi.y);
            }
        }
    }
}

// ---------------- K3: adjacency, 64x64 symmetric tile pairs, j-split -----------
// grid (10, 8, 2), block (16,16). 4x4 products/thread, double-buffered.
__global__ void a_kernel() {
    __shared__ __align__(16) float Si[2][16][68];
    __shared__ __align__(16) float Sk[2][16][68];
    __shared__ float scol[64];
    int tx = threadIdx.x, ty = threadIdx.y;
    int tid = ty*16 + tx;
    int p = blockIdx.x, bh = blockIdx.y, js = blockIdx.z;
    int jbase = js ? 128 : 0;
    int NC = js ? 7 : 8;
    // 10 pairs over 4 tiles of 64: ti <= tk
    int ti = 0, rem = p;
    while (rem >= 4 - ti) { rem -= 4 - ti; ti++; }
    int tk = ti + rem;
    int i0 = ti*64, k0 = tk*64;
    const float* Sb = g_S + (size_t)bh*LL*LP;
    const float THR = 6.4f;   // == 0.1f * 64 exactly in fp32
    if (tid < 64) scol[tid] = 0.f;

    int lr = tid >> 2;            // 0..63
    int lf = (tid & 3) * 4;       // 0,4,8,12
    int irow = i0 + lr, krow = k0 + lr;
    float4 iReg, kReg;

    auto loadc = [&](int c) {
        int jb = jbase + c*16 + lf;
        iReg = (irow < LL) ? ld4(Sb + irow*LP + jb) : f4z();
        kReg = (krow < LL) ? ld4(Sb + krow*LP + jb) : f4z();
    };
    auto storec = [&](int st) {
        Si[st][lf+0][lr] = iReg.x; Si[st][lf+1][lr] = iReg.y;
        Si[st][lf+2][lr] = iReg.z; Si[st][lf+3][lr] = iReg.w;
        Sk[st][lf+0][lr] = kReg.x; Sk[st][lf+1][lr] = kReg.y;
        Sk[st][lf+2][lr] = kReg.z; Sk[st][lf+3][lr] = kReg.w;
    };

    float a[4][4] = {};
    loadc(0); storec(0); __syncthreads();
    for (int c = 0; c < NC; c++) {
        int st = c & 1;
        if (c + 1 < NC) loadc(c + 1);
#pragma unroll
        for (int kk = 0; kk < 16; kk++) {
            float4 a4 = *(const float4*)&Si[st][kk][ty*4];
            float4 b4 = *(const float4*)&Sk[st][kk][tx*4];
            unsigned long long b01 = pk2(b4.x, b4.y);
            unsigned long long b23 = pk2(b4.z, b4.w);
#pragma unroll
            for (int r = 0; r < 4; r++) {
                float ar = (r == 0) ? a4.x : (r == 1) ? a4.y : (r == 2) ? a4.z : a4.w;
                unsigned long long aa = pk2(ar, ar);
                float2 f0 = up2(mul2(aa, b01));
                float2 f1 = up2(mul2(aa, b23));
                if (f0.x > THR) a[r][0] += f0.x;
                if (f0.y > THR) a[r][1] += f0.y;
                if (f1.x > THR) a[r][2] += f1.x;
                if (f1.y > THR) a[r][3] += f1.y;
            }
        }
        if (c + 1 < NC) storec(st ^ 1);
        __syncthreads();
    }

    const float sc = 1.f / (64.f * 225.f);
    int ig0 = i0 + ty*4, kg0 = k0 + tx*4;
    float av[4][4];
#pragma unroll
    for (int r = 0; r < 4; r++)
#pragma unroll
        for (int c = 0; c < 4; c++) {
            float v = a[r][c] * sc;
            av[r][c] = (ig0 + r == kg0 + c) ? 0.f : v;
        }
    float* Ab = (js ? g_A1 : g_A0) + (size_t)bh*LL*LP;
    // direct store (float4 rows)
    if (kg0 + 3 < LP) {
#pragma unroll
        for (int r = 0; r < 4; r++) {
            int ig = ig0 + r;
            if (ig < LL)
                *(float4*)(Ab + ig*LP + kg0) =
                    make_float4(av[r][0], av[r][1], av[r][2], av[r][3]);
        }
    }
    // mirror store (ti<tk implies ig0+3 < LP)
    if (ti != tk) {
#pragma unroll
        for (int c = 0; c < 4; c++) {
            int kg = kg0 + c;
            if (kg < LL)
                *(float4*)(Ab + kg*LP + ig0) =
                    make_float4(av[0][c], av[1][c], av[2][c], av[3][c]);
        }
    }
    // deg rows (reduce across tx: lane = (ty&1)*16 + tx)
#pragma unroll
    for (int r = 0; r < 4; r++) {
        float rs = (av[r][0] + av[r][1]) + (av[r][2] + av[r][3]);
#pragma unroll
        for (int off = 8; off > 0; off >>= 1)
            rs += __shfl_xor_sync(0xffffffffu, rs, off);
        int ig = ig0 + r;
        if (tx == 0 && ig < LL) atomicAdd(&g_deg[bh*LP + ig], rs);
    }
    // deg cols (mirror contribution)
    if (ti != tk) {
#pragma unroll
        for (int c = 0; c < 4; c++) {
            float cs = (av[0][c] + av[1][c]) + (av[2][c] + av[3][c]);
            atomicAdd(&scol[tx*4 + c], cs);
        }
        __syncthreads();
        if (tid < 64) {
            int kg = k0 + tid;
            if (kg < LL) atomicAdd(&g_deg[bh*LP + kg], scol[tid]);
        }
    }
}

// ---------------- K4/K5: 225^3 GEMMs, 64x64 tile, 4x8/thread, k-split ----------
// MODE 0: T = A_hat @ S       MODE 1: P = T @ A_hat / 8  (A_hat symmetric)
// grid (4 j, 4 i, 16 = bh*2 + ks), block (8,16) = 128 threads.
template<int MODE>
__global__ void gemm_kernel() {
    __shared__ __align__(16) float As[2][16][68];
    __shared__ __align__(16) float Bs[2][16][68];
    __shared__ float sdis[LP];
    int tx = threadIdx.x;   // 0..7  (8 cols each)
    int ty = threadIdx.y;   // 0..15 (4 rows each)
    int tid = ty*8 + tx;    // 0..127
    int bh = blockIdx.z >> 1, ks = blockIdx.z & 1;
    int kbase = ks ? 128 : 0;
    int NC = ks ? 7 : 8;
    int i0 = blockIdx.y*64, j0 = blockIdx.x*64;
    for (int t = tid; t < LP; t += 128)
        sdis[t] = rsqrtf(fmaxf(1.f + g_deg[bh*LP + t], 1e-6f));
    size_t off = (size_t)bh*LL*LP;
    const float* Aop0 = ((MODE == 0) ? g_A0 : g_T0) + off;
    const float* Aop1 = ((MODE == 0) ? g_A1 : g_T1) + off;
    const float* Bop0 = ((MODE == 0) ? g_S  : g_A0) + off;
    const float* Bop1 = ((MODE == 0) ? g_S  : g_A1) + off;
    float* Cb = (MODE == 0) ? ((ks ? g_T1 : g_T0) + off)
                            : ((ks ? g_P1 : g_P0) + off);
    __syncthreads();

    int alr = tid >> 1;            // 0..63 (A row within tile)
    int aaf = (tid & 1) * 8;       // kk 0 or 8
    int arow = i0 + alr;
    int bkk = tid >> 3;            // 0..15
    int bj8 = (tid & 7) * 8;
    int bj = j0 + bj8;

    float4 aR0 = f4z(), aR1 = f4z(), bR0 = f4z(), bR1 = f4z();

    auto loadc = [&](int c) {
        int kabs = kbase + c*16;
        if (arow < LL) {
            const float* pr = Aop0 + arow*LP + kabs + aaf;
            const float* pr1 = Aop1 + arow*LP + kabs + aaf;
            float4 u0 = ld4(pr),     w0 = ld4(pr1);
            float4 u1 = ld4(pr + 4), w1 = ld4(pr1 + 4);
            aR0 = make_float4(u0.x + w0.x, u0.y + w0.y, u0.z + w0.z, u0.w + w0.w);
            aR1 = make_float4(u1.x + w1.x, u1.y + w1.y, u1.z + w1.z, u1.w + w1.w);
        } else { aR0 = f4z(); aR1 = f4z(); }
        int k = kabs + bkk;
        if (k < LL && bj < LP) {
            bR0 = ld4(Bop0 + k*LP + bj);
            bR1 = ld4(Bop0 + k*LP + bj + 4);
            if (MODE == 1) {
                float4 w0 = ld4(Bop1 + k*LP + bj);
                float4 w1 = ld4(Bop1 + k*LP + bj + 4);
                bR0.x += w0.x; bR0.y += w0.y; bR0.z += w0.z; bR0.w += w0.w;
                bR1.x += w1.x; bR1.y += w1.y; bR1.z += w1.z; bR1.w += w1.w;
            }
        } else { bR0 = f4z(); bR1 = f4z(); }
    };
    auto storec = [&](int st, int c) {
        int kabs = kbase + c*16;
        float4 v0 = aR0, v1 = aR1;
        if (MODE == 0) {
            int kb = kabs + aaf;
            float4 d0 = *(const float4*)&sdis[kb];
            float4 d1 = *(const float4*)&sdis[kb + 4];
            v0.x *= d0.x; v0.y *= d0.y; v0.z *= d0.z; v0.w *= d0.w;
            v1.x *= d1.x; v1.y *= d1.y; v1.z *= d1.z; v1.w *= d1.w;
            if (arow < LL) {
                int dj = arow - kb;
                if (dj == 0) v0.x += d0.x; else if (dj == 1) v0.y += d0.y;
                else if (dj == 2) v0.z += d0.z; else if (dj == 3) v0.w += d0.w;
                else if (dj == 4) v1.x += d1.x; else if (dj == 5) v1.y += d1.y;
                else if (dj == 6) v1.z += d1.z; else if (dj == 7) v1.w += d1.w;
            }
        }
        As[st][aaf+0][alr] = v0.x; As[st][aaf+1][alr] = v0.y;
        As[st][aaf+2][alr] = v0.z; As[st][aaf+3][alr] = v0.w;
        As[st][aaf+4][alr] = v1.x; As[st][aaf+5][alr] = v1.y;
        As[st][aaf+6][alr] = v1.z; As[st][aaf+7][alr] = v1.w;
        float4 w0 = bR0, w1 = bR1;
        if (MODE == 1) {
            int k = kabs + bkk;
            float dk = (k < LL) ? sdis[k] : 0.f;
            w0.x *= dk; w0.y *= dk; w0.z *= dk; w0.w *= dk;
            w1.x *= dk; w1.y *= dk; w1.z *= dk; w1.w *= dk;
            int dj = k - bj;
            if (dj == 0) w0.x += dk; else if (dj == 1) w0.y += dk;
            else if (dj == 2) w0.z += dk; else if (dj == 3) w0.w += dk;
            else if (dj == 4) w1.x += dk; else if (dj == 5) w1.y += dk;
            else if (dj == 6) w1.z += dk; else if (dj == 7) w1.w += dk;
        }
        *(float4*)&Bs[st][bkk][bj8]     = w0;
        *(float4*)&Bs[st][bkk][bj8 + 4] = w1;
    };

    unsigned long long acc[4][4] = {};
    loadc(0); storec(0, 0); __syncthreads();
    for (int c = 0; c < NC; c++) {
        int st = c & 1;
        if (c + 1 < NC) loadc(c + 1);
#pragma unroll
        for (int kk = 0; kk < 16; kk++) {
            float4 a4 = *(const float4*)&As[st][kk][ty*4];
            const ulonglong2* bp = (const ulonglong2*)&Bs[st][kk][tx*8];
            ulonglong2 b01 = bp[0], b23 = bp[1];
            unsigned long long aa;
            aa = pk2(a4.x, a4.x);
            fma2(acc[0][0], aa, b01.x); fma2(acc[0][1], aa, b01.y);
            fma2(acc[0][2], aa, b23.x); fma2(acc[0][3], aa, b23.y);
            aa = pk2(a4.y, a4.y);
            fma2(acc[1][0], aa, b01.x); fma2(acc[1][1], aa, b01.y);
            fma2(acc[1][2], aa, b23.x); fma2(acc[1][3], aa, b23.y);
            aa = pk2(a4.z, a4.z);
            fma2(acc[2][0], aa, b01.x); fma2(acc[2][1], aa, b01.y);
            fma2(acc[2][2], aa, b23.x); fma2(acc[2][3], aa, b23.y);
            aa = pk2(a4.w, a4.w);
            fma2(acc[3][0], aa, b01.x); fma2(acc[3][1], aa, b01.y);
            fma2(acc[3][2], aa, b23.x); fma2(acc[3][3], aa, b23.y);
        }
        if (c + 1 < NC) storec(st ^ 1, c + 1);
        __syncthreads();
    }

    int jc = j0 + tx*8;
    if (jc < LP) {
        float4 sj0 = make_float4(1.f, 1.f, 1.f, 1.f), sj1 = sj0;
        if (MODE == 1) {
            sj0 = *(const float4*)&sdis[jc];
            sj1 = *(const float4*)&sdis[jc + 4];
        }
#pragma unroll
        for (int r = 0; r < 4; r++) {
            int i = i0 + ty*4 + r;
            if (i < LL) {
                float2 p0 = up2(acc[r][0]), p1 = up2(acc[r][1]);
                float2 p2 = up2(acc[r][2]), p3 = up2(acc[r][3]);
                float4 o0 = make_float4(p0.x, p0.y, p1.x, p1.y);
                float4 o1 = make_float4(p2.x, p2.y, p3.x, p3.y);
                if (MODE == 0) {
                    float di = sdis[i];
                    o0.x *= di; o0.y *= di; o0.z *= di; o0.w *= di;
                    o1.x *= di; o1.y *= di; o1.z *= di; o1.w *= di;
                } else {
                    o0.x *= sj0.x * 0.125f; o0.y *= sj0.y * 0.125f;
                    o0.z *= sj0.z * 0.125f; o0.w *= sj0.w * 0.125f;
                    o1.x *= sj1.x * 0.125f; o1.y *= sj1.y * 0.125f;
                    o1.z *= sj1.z * 0.125f; o1.w *= sj1.w * 0.125f;
                }
                *(float4*)(Cb + i*LP + jc)     = o0;
                *(float4*)(Cb + i*LP + jc + 4) = o1;
            }
        }
    }
}

// ---------------- K6: fused softmax + O = attn @ v (P = P0 + P1) ----------------
// grid (15, 8), block (16,16). 16-row tiles, 64 output cols (= HD).
__global__ void av_kernel() {
    __shared__ __align__(16) float2 PsD[16][18];
    __shared__ __align__(16) float  Vs[16][68];
    __shared__ float smx[16], sinv[16];
    int tx = threadIdx.x, ty = threadIdx.y;
    int tid = ty*16 + tx;
    int bh = blockIdx.y;
    int i0 = blockIdx.x*16;
    const float* P0 = g_P0 + (size_t)bh*LL*LP;
    const float* P1 = g_P1 + (size_t)bh*LL*LP;
    const float* Vb = g_v + bh*LL*HD;
    {
        int w = tid >> 5, lane = tid & 31;
#pragma unroll
        for (int rr = 0; rr < 2; rr++) {
            int row = w*2 + rr;
            int i = i0 + row;
            if (i < LL) {
                const float* Pr0 = P0 + i*LP;
                const float* Pr1 = P1 + i*LP;
                float vb[8];
                float m = -1e30f;
#pragma unroll
                for (int e = 0; e < 8; e++) {
                    int j = lane + 32*e;
                    float v = (j < LL) ? (Pr0[j] + Pr1[j]) : -1e30f;
                    vb[e] = v;
                    m = fmaxf(m, v);
                }
#pragma unroll
                for (int off = 16; off > 0; off >>= 1)
                    m = fmaxf(m, __shfl_xor_sync(0xffffffffu, m, off));
                float s = 0.f;
#pragma unroll
                for (int e = 0; e < 8; e++) s += __expf(vb[e] - m);
#pragma unroll
                for (int off = 16; off > 0; off >>= 1)
                    s += __shfl_xor_sync(0xffffffffu, s, off);
                if (lane == 0) { smx[row] = m; sinv[row] = 1.f / s; }
            }
        }
    }
    __syncthreads();
    unsigned long long acc[2] = {};
    for (int k0 = 0; k0 < LP; k0 += 16) {
        if (tid < 64) {
            int row = tid >> 2, f = (tid & 3)*4;
            int i = i0 + row;
            float4 v;
            if (i < LL) {
                float4 v0 = ld4(P0 + i*LP + k0 + f);
                float4 v1 = ld4(P1 + i*LP + k0 + f);
                float m = smx[row], inv = sinv[row];
                int kb = k0 + f;
                v.x = (kb + 0 < LL) ? __expf(v0.x + v1.x - m)*inv : 0.f;
                v.y = (kb + 1 < LL) ? __expf(v0.y + v1.y - m)*inv : 0.f;
                v.z = (kb + 2 < LL) ? __expf(v0.z + v1.z - m)*inv : 0.f;
                v.w = (kb + 3 < LL) ? __expf(v0.w + v1.w - m)*inv : 0.f;
            } else v = f4z();
            PsD[f+0][row] = make_float2(v.x, v.x);
            PsD[f+1][row] = make_float2(v.y, v.y);
            PsD[f+2][row] = make_float2(v.z, v.z);
            PsD[f+3][row] = make_float2(v.w, v.w);
        }
        { int kk = tid >> 4, d4 = (tid & 15)*4;
          int k = k0 + kk;
          float4 v = (k < LL) ? ld4(Vb + k*HD + d4) : f4z();
          *(float4*)&Vs[kk][d4] = v; }
        __syncthreads();
#pragma unroll
        for (int kk = 0; kk < 16; kk++) {
            unsigned long long a = *(const unsigned long long*)&PsD[kk][ty];
            ulonglong2 b = *(const ulonglong2*)&Vs[kk][tx*4];
            fma2(acc[0], a, b.x);
            fma2(acc[1], a, b.y);
        }
        __syncthreads();
    }
    int b = bh >> 2, h = bh & 3;
    int i = i0 + ty;
    if (i < LL) {
        float2 lo = up2(acc[0]), hi = up2(acc[1]);
        *(float4*)(g_O + (b*LL + i)*DD + h*HD + tx*4) =
            make_float4(lo.x, lo.y, hi.x, hi.y);
    }
}

// ---------------- K7: out = O @ Wo^T ---------------------------------------------
__global__ void out_kernel(const float* __restrict__ Wo, float* __restrict__ out) {
    __shared__ __align__(16) float Os[32][20];
    __shared__ __align__(16) float Ws[16][68];
    int tx = threadIdx.x, ty = threadIdx.y;
    int tid = ty*16 + tx;
    int m0 = blockIdx.y*32, c0 = blockIdx.x*64;
    unsigned long long acc[2][2] = {};
    for (int k0 = 0; k0 < 256; k0 += 16) {
        if (tid < 128) {
            int ii = tid >> 2, f = tid & 3;
            int m = m0 + ii;
            float4 v = (m < NROW) ? ld4(g_O + m*256 + k0 + 4*f) : f4z();
            *(float4*)&Os[ii][4*f] = v;
        } else {
#pragma unroll
            for (int s2 = 0; s2 < 2; s2++) {
                int idx = (tid - 128) + 128*s2;
                int ll = idx >> 2, f = idx & 3;
                float4 w = ld4(Wo + (c0 + ll)*256 + k0 + 4*f);
                Ws[4*f+0][ll] = w.x; Ws[4*f+1][ll] = w.y;
                Ws[4*f+2][ll] = w.z; Ws[4*f+3][ll] = w.w;
            }
        }
        __syncthreads();
        inner16_2<20, 68>(&Os[0][0], &Ws[0][0], ty*2, tx*4, acc);
        __syncthreads();
    }
#pragma unroll
    for (int r = 0; r < 2; r++) {
        int m = m0 + ty*2 + r;
        if (m < NROW) {
            float2 lo = up2(acc[r][0]), hi = up2(acc[r][1]);
            *(float4*)(out + m*256 + c0 + tx*4) =
                make_float4(lo.x, lo.y, hi.x, hi.y);
        }
    }
}

// ---------------- launcher --------------------------------------------------------
extern "C" void kernel_launch(void* const* d_in, const int* in_sizes, int n_in,
                              void* d_out, int out_size) {
    const float* x  = (const float*)d_in[0];
    const float* Wq = (const float*)d_in[1];
    const float* Wk = (const float*)d_in[2];
    const float* Wv = (const float*)d_in[3];
    const float* Wo = (const float*)d_in[4];
    float* out = (float*)d_out;

    dim3 b16(16, 16), b168(16, 8), bg(8, 16);

    qkv_kernel<<<dim3(12, 15), b168>>>(x, Wq, Wk, Wv);
    s_kernel<<<dim3(4, 4, 8), b16>>>();
    a_kernel<<<dim3(10, 8, 2), b16>>>();
    gemm_kernel<0><<<dim3(4, 4, 16), bg>>>();
    gemm_kernel<1><<<dim3(4, 4, 16), bg>>>();
    av_kernel<<<dim3(15, 8), b16>>>();
    out_kernel<<<dim3(4, 15), b16>>>(Wo, out);
}